// round 6
// baseline (speedup 1.0000x reference)
#include <cuda_runtime.h>
#include <cuda_bf16.h>
#include <float.h>
#include <stdint.h>

// ---------------------------------------------------------------------------
// Problem constants
#define BB   32
#define CC   256
#define HWD  1024
#define KK   1024
#define NN   (BB * HWD)        // 32768
#define BM   128               // query rows per CTA
#define NCHUNK 96              // 8 nt * 3 bc(w-comp) * 4 kc

// SMEM layout (dynamic)
#define SM_A        0                   // 3 comps x [128 m][256 k] bf16 (swizzled) = 3*65536
#define SM_A_COMP   65536
#define SM_B        196608              // 2 bufs x [128 n][64 k] bf16 (swizzled) = 2*16384
#define SM_B_BUF    16384
#define SMEM_TOTAL  229376
// reduction overlays B region (B is dead by then)
#define SM_REDV     SM_B                // 128*4 floats
#define SM_REDI     (SM_B + 2048)       // 128*4 ints
#define SM_RIDX     (SM_B + 4096)       // 128 ints

// ---------------------------------------------------------------------------
// Device scratch (static globals — no allocation). 16B-aligned for cp.async.
__device__ __align__(256) __nv_bfloat16 g_wb[3][KK * CC];   // w comps [n][k]
__device__ __align__(256) __nv_bfloat16 g_zb[3][NN * CC];   // z comps [m][k]
__device__ float g_wsq[KK];

// ---------------------------------------------------------------------------
__device__ __forceinline__ uint32_t smem_u32(const void* p) {
    return (uint32_t)__cvta_generic_to_shared(p);
}
__device__ __forceinline__ void cpa16(uint32_t s, const void* g) {
    asm volatile("cp.async.cg.shared.global [%0], [%1], 16;\n" :: "r"(s), "l"(g));
}
#define CPA_COMMIT() asm volatile("cp.async.commit_group;\n" ::: "memory")
#define CPA_WAIT(n)  asm volatile("cp.async.wait_group %0;\n" :: "n"(n) : "memory")

__device__ __forceinline__ void ldsm4(uint32_t* r, uint32_t addr) {
    asm volatile("ldmatrix.sync.aligned.m8n8.x4.shared.b16 {%0,%1,%2,%3}, [%4];"
                 : "=r"(r[0]), "=r"(r[1]), "=r"(r[2]), "=r"(r[3]) : "r"(addr));
}
__device__ __forceinline__ void mma16816(float* d, const uint32_t* a,
                                         uint32_t b0, uint32_t b1) {
    asm volatile("mma.sync.aligned.m16n8k16.row.col.f32.bf16.bf16.f32 "
                 "{%0,%1,%2,%3}, {%4,%5,%6,%7}, {%8,%9}, {%0,%1,%2,%3};"
                 : "+f"(d[0]), "+f"(d[1]), "+f"(d[2]), "+f"(d[3])
                 : "r"(a[0]), "r"(a[1]), "r"(a[2]), "r"(a[3]), "r"(b0), "r"(b1));
}

// ---------------------------------------------------------------------------
// Prep: split w into 3 bf16 components
__global__ void split_w_kernel(const float* __restrict__ w) {
    int idx = blockIdx.x * 256 + threadIdx.x;
    float v = w[idx];
    __nv_bfloat16 b1 = __float2bfloat16_rn(v);
    float r1 = v - __bfloat162float(b1);
    __nv_bfloat16 b2 = __float2bfloat16_rn(r1);
    float r2 = r1 - __bfloat162float(b2);
    __nv_bfloat16 b3 = __float2bfloat16_rn(r2);
    g_wb[0][idx] = b1; g_wb[1][idx] = b2; g_wb[2][idx] = b3;
}

// ||e_k||^2 per code, one warp per code
__global__ void wsq_kernel(const float* __restrict__ w) {
    int code = blockIdx.x * 8 + (threadIdx.x >> 5);
    int lane = threadIdx.x & 31;
    const float* row = w + (size_t)code * CC;
    float s = 0.f;
    #pragma unroll
    for (int c = lane; c < CC; c += 32) { float v = row[c]; s += v * v; }
    #pragma unroll
    for (int o = 16; o; o >>= 1) s += __shfl_down_sync(0xffffffffu, s, o);
    if (lane == 0) g_wsq[code] = s;
}

// Split + transpose z: z[b][c][hw] -> g_zb[comp][m = b*1024+hw][c]
__global__ void split_z_kernel(const float* __restrict__ z) {
    __shared__ float t[32][33];
    int c0  = blockIdx.x * 32;
    int hw0 = blockIdx.y * 32;
    int b   = blockIdx.z;
    int x = threadIdx.x, y0 = threadIdx.y;     // 32 x 8
    const float* zb = z + ((size_t)b * CC) * HWD;
    #pragma unroll
    for (int yy = 0; yy < 32; yy += 8)
        t[y0 + yy][x] = zb[(size_t)(c0 + y0 + yy) * HWD + hw0 + x];
    __syncthreads();
    #pragma unroll
    for (int yy = 0; yy < 32; yy += 8) {
        int hwl = y0 + yy;
        float v = t[x][hwl];
        size_t o = (size_t)(b * HWD + hw0 + hwl) * CC + c0 + x;
        __nv_bfloat16 b1 = __float2bfloat16_rn(v);
        float r1 = v - __bfloat162float(b1);
        __nv_bfloat16 b2 = __float2bfloat16_rn(r1);
        float r2 = r1 - __bfloat162float(b2);
        __nv_bfloat16 b3 = __float2bfloat16_rn(r2);
        g_zb[0][o] = b1; g_zb[1][o] = b2; g_zb[2][o] = b3;
    }
}

// ---------------------------------------------------------------------------
// B chunk loader: chunk c = nt*12 + bc*4 + kc -> [128 n][64 k] bf16, swizzled
__device__ __forceinline__ void load_b_chunk(uint32_t Bbase, int c, int buf, int tid) {
    int nt = c / 12, pos = c % 12, bc = pos >> 2, kc = pos & 3;
    const __nv_bfloat16* base = g_wb[bc] + ((size_t)(nt * 128) << 8) + (kc << 6);
    uint32_t dst = Bbase + buf * SM_B_BUF;
    #pragma unroll
    for (int j = 0; j < 2; ++j) {
        int gi = j * 512 + tid;            // 0..1023 granules
        int r = gi >> 3, g = gi & 7;
        cpa16(dst + r * 128 + ((g ^ (r & 7)) << 4),
              base + ((size_t)r << 8) + (g << 3));
    }
}

// ---------------------------------------------------------------------------
// Fused HMMA GEMM + argmin + gather + write. 512 threads, 1 CTA/SM.
// Warp grid 4(m) x 4(n); warp tile 32m x 32n.
__global__ __launch_bounds__(512, 1)
void vq_kernel(const float* __restrict__ z,
               const float* __restrict__ w,
               float* __restrict__ out) {
    extern __shared__ __align__(1024) char smem[];
    const int tid  = threadIdx.x;
    const int lane = tid & 31;
    const int wid  = tid >> 5;
    const int wm   = wid >> 2;     // 0..3 : m-warp (32 rows each)
    const int wn   = wid & 3;      // 0..3 : n-warp (32 cols each)

    const int n0  = blockIdx.x * BM;
    const int b   = n0 >> 10;
    const int hw0 = n0 & (HWD - 1);

    const uint32_t sbase = smem_u32(smem);
    const uint32_t Abase = sbase + SM_A;
    const uint32_t Bbase = sbase + SM_B;

    // ---- prologue: resident A (3 comps) + B chunk 0, one cp.async group ----
    #pragma unroll
    for (int j = 0; j < 24; ++j) {
        int gi = j * 512 + tid;            // 0..12287 granules
        int comp = gi >> 12;
        int rem  = gi & 4095;
        int m = rem >> 5, g = rem & 31;
        cpa16(Abase + comp * SM_A_COMP + m * 512 + ((g ^ (m & 7)) << 4),
              g_zb[comp] + ((size_t)(n0 + m) << 8) + (g << 3));
    }
    load_b_chunk(Bbase, 0, 0, tid);
    CPA_COMMIT();

    // per-thread ldmatrix address components
    const uint32_t a_row = wm * 32 + (lane & 15);
    const uint32_t a_ghi = lane >> 4;
    const uint32_t a_rx  = a_row & 7;
    const uint32_t a_addr0 = Abase + a_row * 512;     // + ac*65536 + mf*8192 + gsw*16

    uint32_t b_addr0[2], b_gx[2];                      // per bl(16n)
    #pragma unroll
    for (int bl = 0; bl < 2; ++bl) {
        uint32_t nr = wn * 32 + bl * 16 + (lane & 15);
        b_addr0[bl] = Bbase + nr * 128;
        b_gx[bl] = nr & 7;
    }

    float acc[2][4][4];
    float bestv[4];
    int   besti[4];
    #pragma unroll
    for (int i = 0; i < 4; ++i) { bestv[i] = FLT_MAX; besti[i] = 0; }

    // ---- main loop over 96 chunks ----
    for (int c = 0; c < NCHUNK; ++c) {
        const int nt  = c / 12;
        const int pos = c % 12;
        const int bc  = pos >> 2;
        const int kc  = pos & 3;
        const int buf = c & 1;
        const int nac = 3 - bc;    // w1:{x1,x2,x3} w2:{x1,x2} w3:{x1}

        if (c + 1 < NCHUNK) {
            load_b_chunk(Bbase, c + 1, buf ^ 1, tid);
            CPA_COMMIT();
            CPA_WAIT(1);
        } else {
            CPA_WAIT(0);
        }
        __syncthreads();

        if (pos == 0) {
            #pragma unroll
            for (int i = 0; i < 2; ++i)
                #pragma unroll
                for (int j = 0; j < 4; ++j)
                    #pragma unroll
                    for (int d = 0; d < 4; ++d) acc[i][j][d] = 0.f;
        }

        // compute: two k-halves of the 64k chunk
        #pragma unroll
        for (int kh = 0; kh < 2; ++kh) {
            uint32_t bfr[2][2][4];
            #pragma unroll
            for (int ks2 = 0; ks2 < 2; ++ks2) {
                int ks = kh * 2 + ks2;
                #pragma unroll
                for (int bl = 0; bl < 2; ++bl) {
                    uint32_t g = ks * 2 + a_ghi;
                    ldsm4(bfr[ks2][bl],
                          b_addr0[bl] + buf * SM_B_BUF + ((g ^ b_gx[bl]) << 4));
                }
            }
            for (int ac = 0; ac < nac; ++ac) {
                #pragma unroll
                for (int ks2 = 0; ks2 < 2; ++ks2) {
                    int ks = kh * 2 + ks2;
                    uint32_t g = kc * 8 + ks * 2 + a_ghi;
                    uint32_t off = ((g ^ a_rx) << 4);
                    uint32_t afr[2][4];
                    ldsm4(afr[0], a_addr0 + ac * SM_A_COMP + off);
                    ldsm4(afr[1], a_addr0 + ac * SM_A_COMP + 8192 + off);
                    #pragma unroll
                    for (int mf = 0; mf < 2; ++mf)
                        #pragma unroll
                        for (int bl = 0; bl < 2; ++bl) {
                            mma16816(acc[mf][bl * 2],     afr[mf],
                                     bfr[ks2][bl][0], bfr[ks2][bl][2]);
                            mma16816(acc[mf][bl * 2 + 1], afr[mf],
                                     bfr[ks2][bl][1], bfr[ks2][bl][3]);
                        }
                }
            }
        }

        // fold argmin once the n-tile's 1536-k accumulation is complete
        if (pos == 11) {
            int nb = nt * 128 + wn * 32 + ((lane & 3) << 1);
            #pragma unroll
            for (int mf = 0; mf < 2; ++mf)
                #pragma unroll
                for (int nf = 0; nf < 4; ++nf) {
                    int nidx = nb + nf * 8;
                    float w0 = __ldg(&g_wsq[nidx]);
                    float w1 = __ldg(&g_wsq[nidx + 1]);
                    float s;
                    s = w0 - 2.f * acc[mf][nf][0];
                    if (s < bestv[mf*2])   { bestv[mf*2]   = s; besti[mf*2]   = nidx; }
                    s = w1 - 2.f * acc[mf][nf][1];
                    if (s < bestv[mf*2])   { bestv[mf*2]   = s; besti[mf*2]   = nidx + 1; }
                    s = w0 - 2.f * acc[mf][nf][2];
                    if (s < bestv[mf*2+1]) { bestv[mf*2+1] = s; besti[mf*2+1] = nidx; }
                    s = w1 - 2.f * acc[mf][nf][3];
                    if (s < bestv[mf*2+1]) { bestv[mf*2+1] = s; besti[mf*2+1] = nidx + 1; }
                }
        }
        __syncthreads();
    }

    // ---- argmin reduce: across 4 lanes sharing rows, then across 4 n-warps ----
    float* redv = (float*)(smem + SM_REDV);
    int*   redi = (int*)(smem + SM_REDI);
    int*   ridx = (int*)(smem + SM_RIDX);
    #pragma unroll
    for (int slot = 0; slot < 4; ++slot) {
        float v = bestv[slot];
        int  id = besti[slot];
        #pragma unroll
        for (int m = 1; m <= 2; m <<= 1) {
            float ov = __shfl_xor_sync(0xffffffffu, v, m);
            int   oi = __shfl_xor_sync(0xffffffffu, id, m);
            if (ov < v || (ov == v && oi < id)) { v = ov; id = oi; }
        }
        if ((lane & 3) == 0) {
            int row = wm * 32 + (slot >> 1) * 16 + (lane >> 2) + ((slot & 1) << 3);
            redv[row * 4 + wn] = v;
            redi[row * 4 + wn] = id;
        }
    }
    __syncthreads();
    if (tid < BM) {
        float v = redv[tid * 4];
        int  id = redi[tid * 4];
        #pragma unroll
        for (int j = 1; j < 4; ++j) {
            float ov = redv[tid * 4 + j];
            int   oi = redi[tid * 4 + j];
            if (ov < v || (ov == v && oi < id)) { v = ov; id = oi; }
        }
        ridx[tid] = id;
    }
    __syncthreads();

    // ---- output epilogue: gather q into smem (overlay A), write both outputs ----
    float* qs = (float*)(smem + SM_A);       // [256 c][128 m] fp32
    {
        int m = tid & 127;
        int cpart = tid >> 7;                // 0..3 (c quarters)
        const float4* wr = (const float4*)(w + (size_t)ridx[m] * CC + cpart * 64);
        #pragma unroll
        for (int g = 0; g < 16; ++g) {
            float4 v = wr[g];
            int cq = cpart * 64 + g * 4;
            qs[(cq + 0) * BM + m] = v.x;
            qs[(cq + 1) * BM + m] = v.y;
            qs[(cq + 2) * BM + m] = v.z;
            qs[(cq + 3) * BM + m] = v.w;
        }
    }
    __syncthreads();
    {
        float* out_codes = out;
        float* out_bar   = out + (size_t)NN * CC;
        const int cg = tid >> 5;             // 0..15
        const int r4 = (tid & 31) * 4;
        #pragma unroll 4
        for (int cc = 0; cc < 16; ++cc) {
            int cq = cg * 16 + cc;
            size_t zo = ((size_t)(b * CC + cq)) * HWD + hw0 + r4;
            float4 zv = *(const float4*)(z + zo);
            float4 q  = *(const float4*)(qs + cq * BM + r4);
            float4 co;
            co.x = zv.x + (q.x - zv.x);
            co.y = zv.y + (q.y - zv.y);
            co.z = zv.z + (q.z - zv.z);
            co.w = zv.w + (q.w - zv.w);
            *(float4*)(out_codes + zo) = co;
            *(float4*)(out_bar   + zo) = q;
        }
    }
}

// ---------------------------------------------------------------------------
extern "C" void kernel_launch(void* const* d_in, const int* in_sizes, int n_in,
                              void* d_out, int out_size) {
    const float* z = (const float*)d_in[0];
    const float* w = (const float*)d_in[1];
    if (n_in >= 2 && in_sizes[0] == KK * CC && in_sizes[1] == NN * CC) {
        const float* t = z; z = w; w = t;
    }
    float* out = (float*)d_out;

    static bool attr_set = false;
    if (!attr_set) {
        cudaFuncSetAttribute(vq_kernel, cudaFuncAttributeMaxDynamicSharedMemorySize,
                             SMEM_TOTAL);
        attr_set = true;
    }

    split_w_kernel<<<KK * CC / 256, 256>>>(w);
    wsq_kernel<<<KK / 8, 256>>>(w);
    split_z_kernel<<<dim3(CC / 32, HWD / 32, BB), dim3(32, 8)>>>(z);
    vq_kernel<<<NN / BM, 512, SMEM_TOTAL>>>(z, w, out);
}

// round 7
// speedup vs baseline: 1.7997x; 1.7997x over previous
#include <cuda_runtime.h>
#include <cuda_fp16.h>
#include <float.h>
#include <stdint.h>

// ---------------------------------------------------------------------------
// Problem constants
#define BB   32
#define CC   256
#define HWD  1024
#define KK   1024
#define NN   (BB * HWD)        // 32768
#define BM   128               // query rows per CTA
#define NCHUNK 64              // 8 nt * 2 bc(w-comp) * 4 kc

// SMEM layout (dynamic)
#define SM_A        0                   // 2 comps x [128 m][256 k] fp16 (swizzled) = 2*65536
#define SM_A_COMP   65536
#define SM_B        131072              // 2 bufs x [128 n][64 k] fp16 (swizzled) = 2*16384
#define SM_B_BUF    16384
#define SMEM_TOTAL  163840
// reduction overlays B region (B is dead by then)
#define SM_REDV     SM_B                // 128*4 floats
#define SM_REDI     (SM_B + 2048)       // 128*4 ints
#define SM_RIDX     (SM_B + 4096)       // 128 ints

// ---------------------------------------------------------------------------
// Device scratch (static globals — no allocation). 16B-aligned for cp.async.
__device__ __align__(256) __half g_wb[2][KK * CC];   // w comps [n][k]
__device__ __align__(256) __half g_zb[2][NN * CC];   // z comps [m][k]
__device__ float g_wsq[KK];

// ---------------------------------------------------------------------------
__device__ __forceinline__ uint32_t smem_u32(const void* p) {
    return (uint32_t)__cvta_generic_to_shared(p);
}
__device__ __forceinline__ void cpa16(uint32_t s, const void* g) {
    asm volatile("cp.async.cg.shared.global [%0], [%1], 16;\n" :: "r"(s), "l"(g));
}
#define CPA_COMMIT() asm volatile("cp.async.commit_group;\n" ::: "memory")
#define CPA_WAIT(n)  asm volatile("cp.async.wait_group %0;\n" :: "n"(n) : "memory")

__device__ __forceinline__ void ldsm4(uint32_t* r, uint32_t addr) {
    asm volatile("ldmatrix.sync.aligned.m8n8.x4.shared.b16 {%0,%1,%2,%3}, [%4];"
                 : "=r"(r[0]), "=r"(r[1]), "=r"(r[2]), "=r"(r[3]) : "r"(addr));
}
__device__ __forceinline__ void mma16816(float* d, const uint32_t* a,
                                         uint32_t b0, uint32_t b1) {
    asm volatile("mma.sync.aligned.m16n8k16.row.col.f32.f16.f16.f32 "
                 "{%0,%1,%2,%3}, {%4,%5,%6,%7}, {%8,%9}, {%0,%1,%2,%3};"
                 : "+f"(d[0]), "+f"(d[1]), "+f"(d[2]), "+f"(d[3])
                 : "r"(a[0]), "r"(a[1]), "r"(a[2]), "r"(a[3]), "r"(b0), "r"(b1));
}

// ---------------------------------------------------------------------------
// Prep: split w into 2 fp16 components
__global__ void split_w_kernel(const float* __restrict__ w) {
    int idx = blockIdx.x * 256 + threadIdx.x;
    float v = w[idx];
    __half h1 = __float2half_rn(v);
    float r1 = v - __half2float(h1);
    __half h2 = __float2half_rn(r1);
    g_wb[0][idx] = h1; g_wb[1][idx] = h2;
}

// ||e_k||^2 per code, one warp per code (exact fp32)
__global__ void wsq_kernel(const float* __restrict__ w) {
    int code = blockIdx.x * 8 + (threadIdx.x >> 5);
    int lane = threadIdx.x & 31;
    const float* row = w + (size_t)code * CC;
    float s = 0.f;
    #pragma unroll
    for (int c = lane; c < CC; c += 32) { float v = row[c]; s += v * v; }
    #pragma unroll
    for (int o = 16; o; o >>= 1) s += __shfl_down_sync(0xffffffffu, s, o);
    if (lane == 0) g_wsq[code] = s;
}

// Split + transpose z: z[b][c][hw] -> g_zb[comp][m = b*1024+hw][c]
__global__ void split_z_kernel(const float* __restrict__ z) {
    __shared__ float t[32][33];
    int c0  = blockIdx.x * 32;
    int hw0 = blockIdx.y * 32;
    int b   = blockIdx.z;
    int x = threadIdx.x, y0 = threadIdx.y;     // 32 x 8
    const float* zb = z + ((size_t)b * CC) * HWD;
    #pragma unroll
    for (int yy = 0; yy < 32; yy += 8)
        t[y0 + yy][x] = zb[(size_t)(c0 + y0 + yy) * HWD + hw0 + x];
    __syncthreads();
    #pragma unroll
    for (int yy = 0; yy < 32; yy += 8) {
        int hwl = y0 + yy;
        float v = t[x][hwl];
        size_t o = (size_t)(b * HWD + hw0 + hwl) * CC + c0 + x;
        __half h1 = __float2half_rn(v);
        float r1 = v - __half2float(h1);
        __half h2 = __float2half_rn(r1);
        g_zb[0][o] = h1; g_zb[1][o] = h2;
    }
}

// ---------------------------------------------------------------------------
// B chunk loader: chunk c = nt*8 + bc*4 + kc -> [128 n][64 k] fp16, swizzled
__device__ __forceinline__ void load_b_chunk(uint32_t Bbase, int c, int buf, int tid) {
    int nt = c >> 3, pos = c & 7, bc = pos >> 2, kc = pos & 3;
    const __half* base = g_wb[bc] + ((size_t)(nt * 128) << 8) + (kc << 6);
    uint32_t dst = Bbase + buf * SM_B_BUF;
    #pragma unroll
    for (int j = 0; j < 2; ++j) {
        int gi = j * 512 + tid;            // 0..1023 granules
        int r = gi >> 3, g = gi & 7;
        cpa16(dst + r * 128 + ((g ^ (r & 7)) << 4),
              base + ((size_t)r << 8) + (g << 3));
    }
}

// ---------------------------------------------------------------------------
// Fused HMMA GEMM + argmin + gather + write. 512 threads, 1 CTA/SM.
// Warp grid 4(m) x 4(n); warp tile 32m x 32n.
__global__ __launch_bounds__(512, 1)
void vq_kernel(const float* __restrict__ z,
               const float* __restrict__ w,
               float* __restrict__ out) {
    extern __shared__ __align__(1024) char smem[];
    const int tid  = threadIdx.x;
    const int lane = tid & 31;
    const int wid  = tid >> 5;
    const int wm   = wid >> 2;     // 0..3 : m-warp (32 rows each)
    const int wn   = wid & 3;      // 0..3 : n-warp (32 cols each)

    const int n0  = blockIdx.x * BM;
    const int b   = n0 >> 10;
    const int hw0 = n0 & (HWD - 1);

    const uint32_t sbase = smem_u32(smem);
    const uint32_t Abase = sbase + SM_A;
    const uint32_t Bbase = sbase + SM_B;

    // ---- prologue: resident A (2 comps) + B chunk 0, one cp.async group ----
    #pragma unroll
    for (int j = 0; j < 16; ++j) {
        int gi = j * 512 + tid;            // 0..8191 granules
        int comp = gi >> 12;
        int rem  = gi & 4095;
        int m = rem >> 5, g = rem & 31;
        cpa16(Abase + comp * SM_A_COMP + m * 512 + ((g ^ (m & 7)) << 4),
              g_zb[comp] + ((size_t)(n0 + m) << 8) + (g << 3));
    }
    load_b_chunk(Bbase, 0, 0, tid);
    CPA_COMMIT();

    // per-thread ldmatrix address components
    const uint32_t a_row = wm * 32 + (lane & 15);
    const uint32_t a_ghi = lane >> 4;
    const uint32_t a_rx  = a_row & 7;
    const uint32_t a_addr0 = Abase + a_row * 512;     // + ac*65536 + mf*8192 + gsw*16

    uint32_t b_addr0[2], b_gx[2];                      // per bl(16n)
    #pragma unroll
    for (int bl = 0; bl < 2; ++bl) {
        uint32_t nr = wn * 32 + bl * 16 + (lane & 15);
        b_addr0[bl] = Bbase + nr * 128;
        b_gx[bl] = nr & 7;
    }

    float acc[2][4][4];
    float bestv[4];
    int   besti[4];
    #pragma unroll
    for (int i = 0; i < 4; ++i) { bestv[i] = FLT_MAX; besti[i] = 0; }

    // ---- main loop over 64 chunks ----
    for (int c = 0; c < NCHUNK; ++c) {
        const int nt  = c >> 3;
        const int pos = c & 7;
        const int bc  = pos >> 2;
        const int kc  = pos & 3;
        const int buf = c & 1;
        const int nac = 2 - bc;    // w1:{x1,x2}  w2:{x1}

        if (c + 1 < NCHUNK) {
            load_b_chunk(Bbase, c + 1, buf ^ 1, tid);
            CPA_COMMIT();
            CPA_WAIT(1);
        } else {
            CPA_WAIT(0);
        }
        __syncthreads();

        if (pos == 0) {
            #pragma unroll
            for (int i = 0; i < 2; ++i)
                #pragma unroll
                for (int j = 0; j < 4; ++j)
                    #pragma unroll
                    for (int d = 0; d < 4; ++d) acc[i][j][d] = 0.f;
        }

        // compute: two k-halves of the 64k chunk
        #pragma unroll
        for (int kh = 0; kh < 2; ++kh) {
            uint32_t bfr[2][2][4];
            #pragma unroll
            for (int ks2 = 0; ks2 < 2; ++ks2) {
                int ks = kh * 2 + ks2;
                #pragma unroll
                for (int bl = 0; bl < 2; ++bl) {
                    uint32_t g = ks * 2 + a_ghi;
                    ldsm4(bfr[ks2][bl],
                          b_addr0[bl] + buf * SM_B_BUF + ((g ^ b_gx[bl]) << 4));
                }
            }
            for (int ac = 0; ac < nac; ++ac) {
                #pragma unroll
                for (int ks2 = 0; ks2 < 2; ++ks2) {
                    int ks = kh * 2 + ks2;
                    uint32_t g = kc * 8 + ks * 2 + a_ghi;
                    uint32_t off = ((g ^ a_rx) << 4);
                    uint32_t afr[2][4];
                    ldsm4(afr[0], a_addr0 + ac * SM_A_COMP + off);
                    ldsm4(afr[1], a_addr0 + ac * SM_A_COMP + 8192 + off);
                    #pragma unroll
                    for (int mf = 0; mf < 2; ++mf)
                        #pragma unroll
                        for (int bl = 0; bl < 2; ++bl) {
                            mma16816(acc[mf][bl * 2],     afr[mf],
                                     bfr[ks2][bl][0], bfr[ks2][bl][2]);
                            mma16816(acc[mf][bl * 2 + 1], afr[mf],
                                     bfr[ks2][bl][1], bfr[ks2][bl][3]);
                        }
                }
            }
        }

        // fold argmin once the n-tile's full-K accumulation is complete
        if (pos == 7) {
            int nb = nt * 128 + wn * 32 + ((lane & 3) << 1);
            #pragma unroll
            for (int mf = 0; mf < 2; ++mf)
                #pragma unroll
                for (int nf = 0; nf < 4; ++nf) {
                    int nidx = nb + nf * 8;
                    float w0 = __ldg(&g_wsq[nidx]);
                    float w1 = __ldg(&g_wsq[nidx + 1]);
                    float s;
                    s = w0 - 2.f * acc[mf][nf][0];
                    if (s < bestv[mf*2])   { bestv[mf*2]   = s; besti[mf*2]   = nidx; }
                    s = w1 - 2.f * acc[mf][nf][1];
                    if (s < bestv[mf*2])   { bestv[mf*2]   = s; besti[mf*2]   = nidx + 1; }
                    s = w0 - 2.f * acc[mf][nf][2];
                    if (s < bestv[mf*2+1]) { bestv[mf*2+1] = s; besti[mf*2+1] = nidx; }
                    s = w1 - 2.f * acc[mf][nf][3];
                    if (s < bestv[mf*2+1]) { bestv[mf*2+1] = s; besti[mf*2+1] = nidx + 1; }
                }
        }
        __syncthreads();
    }

    // ---- argmin reduce: across 4 lanes sharing rows, then across 4 n-warps ----
    float* redv = (float*)(smem + SM_REDV);
    int*   redi = (int*)(smem + SM_REDI);
    int*   ridx = (int*)(smem + SM_RIDX);
    #pragma unroll
    for (int slot = 0; slot < 4; ++slot) {
        float v = bestv[slot];
        int  id = besti[slot];
        #pragma unroll
        for (int m = 1; m <= 2; m <<= 1) {
            float ov = __shfl_xor_sync(0xffffffffu, v, m);
            int   oi = __shfl_xor_sync(0xffffffffu, id, m);
            if (ov < v || (ov == v && oi < id)) { v = ov; id = oi; }
        }
        if ((lane & 3) == 0) {
            int row = wm * 32 + (slot >> 1) * 16 + (lane >> 2) + ((slot & 1) << 3);
            redv[row * 4 + wn] = v;
            redi[row * 4 + wn] = id;
        }
    }
    __syncthreads();
    if (tid < BM) {
        float v = redv[tid * 4];
        int  id = redi[tid * 4];
        #pragma unroll
        for (int j = 1; j < 4; ++j) {
            float ov = redv[tid * 4 + j];
            int   oi = redi[tid * 4 + j];
            if (ov < v || (ov == v && oi < id)) { v = ov; id = oi; }
        }
        ridx[tid] = id;
    }
    __syncthreads();

    // ---- output epilogue: gather q into smem (overlay A), write both outputs ----
    float* qs = (float*)(smem + SM_A);       // [256 c][128 m] fp32
    {
        int m = tid & 127;
        int cpart = tid >> 7;                // 0..3 (c quarters)
        const float4* wr = (const float4*)(w + (size_t)ridx[m] * CC + cpart * 64);
        #pragma unroll
        for (int g = 0; g < 16; ++g) {
            float4 v = wr[g];
            int cq = cpart * 64 + g * 4;
            qs[(cq + 0) * BM + m] = v.x;
            qs[(cq + 1) * BM + m] = v.y;
            qs[(cq + 2) * BM + m] = v.z;
            qs[(cq + 3) * BM + m] = v.w;
        }
    }
    __syncthreads();
    {
        float* out_codes = out;
        float* out_bar   = out + (size_t)NN * CC;
        const int cg = tid >> 5;             // 0..15
        const int r4 = (tid & 31) * 4;
        #pragma unroll 4
        for (int cc = 0; cc < 16; ++cc) {
            int cq = cg * 16 + cc;
            size_t zo = ((size_t)(b * CC + cq)) * HWD + hw0 + r4;
            float4 zv = *(const float4*)(z + zo);
            float4 q  = *(const float4*)(qs + cq * BM + r4);
            float4 co;
            co.x = zv.x + (q.x - zv.x);
            co.y = zv.y + (q.y - zv.y);
            co.z = zv.z + (q.z - zv.z);
            co.w = zv.w + (q.w - zv.w);
            *(float4*)(out_codes + zo) = co;
            *(float4*)(out_bar   + zo) = q;
        }
    }
}

// ---------------------------------------------------------------------------
extern "C" void kernel_launch(void* const* d_in, const int* in_sizes, int n_in,
                              void* d_out, int out_size) {
    const float* z = (const float*)d_in[0];
    const float* w = (const float*)d_in[1];
    if (n_in >= 2 && in_sizes[0] == KK * CC && in_sizes[1] == NN * CC) {
        const float* t = z; z = w; w = t;
    }
    float* out = (float*)d_out;

    static bool attr_set = false;
    if (!attr_set) {
        cudaFuncSetAttribute(vq_kernel, cudaFuncAttributeMaxDynamicSharedMemorySize,
                             SMEM_TOTAL);
        attr_set = true;
    }

    split_w_kernel<<<KK * CC / 256, 256>>>(w);
    wsq_kernel<<<KK / 8, 256>>>(w);
    split_z_kernel<<<dim3(CC / 32, HWD / 32, BB), dim3(32, 8)>>>(z);
    vq_kernel<<<NN / BM, 512, SMEM_TOTAL>>>(z, w, out);
}